// round 3
// baseline (speedup 1.0000x reference)
#include <cuda_runtime.h>

// Problem constants
#define BATCH   8
#define CH      512
#define HEADS   8
#define HD      64          // CH / HEADS
#define GROUPS  32
#define CPG     (CH / GROUPS)   // 16
#define NPIX    1024        // 32*32
#define EPS_GN  1e-6f
#define CHB     8           // (b,h) pairs per attention chunk (S buffer size)

// -------- scratch (device globals — allocation-free rule) ----------
// Keep total small: previous 336 MB OOM'd the container.
__device__ float g_qkv[BATCH * 3 * CH * NPIX];        // 48 MB  qkv projections
__device__ float g_S  [CHB * NPIX * NPIX];            // 32 MB  S chunk (reused 8x)
__device__ float g_ao [BATCH * CH * NPIX];            // 16 MB  attention output
__device__ float g_sc [BATCH * CH];                   // per (b,c) scale for fused GN
__device__ float g_tb [BATCH * CH];                   // per (b,c) shift for fused GN

// =====================================================================
// 1) GroupNorm stats: one block per (b, group). Produces per-channel
//    affine (s, t) so that xn = x*s + t, consumed by the QKV GEMM.
// =====================================================================
__global__ void __launch_bounds__(256) gn_stats_kernel(
    const float* __restrict__ x,
    const float* __restrict__ gamma,
    const float* __restrict__ beta)
{
    const int bg = blockIdx.x;
    const int b  = bg / GROUPS;
    const int g  = bg % GROUPS;
    const int elems = CPG * NPIX;   // 16384
    const float* xp = x + ((size_t)b * CH + g * CPG) * NPIX;

    float s = 0.f, sq = 0.f;
    for (int i = threadIdx.x; i < elems; i += 256) {
        float v = xp[i];
        s += v; sq += v * v;
    }
    __shared__ float rs[256], rq[256];
    rs[threadIdx.x] = s; rq[threadIdx.x] = sq;
    __syncthreads();
    for (int st = 128; st > 0; st >>= 1) {
        if (threadIdx.x < st) {
            rs[threadIdx.x] += rs[threadIdx.x + st];
            rq[threadIdx.x] += rq[threadIdx.x + st];
        }
        __syncthreads();
    }
    const float mean = rs[0] * (1.f / elems);
    const float var  = rq[0] * (1.f / elems) - mean * mean;
    const float inv  = rsqrtf(var + EPS_GN);

    if (threadIdx.x < CPG) {
        const int ch = g * CPG + threadIdx.x;
        const float sc = inv * gamma[ch];
        g_sc[b * CH + ch] = sc;
        g_tb[b * CH + ch] = beta[ch] - mean * sc;
    }
}

// =====================================================================
// 2) Weight GEMM: C[b][o][n] = sum_c W[o][c]*(X[b][c][n]*s+t) + bias[o] (+res)
//    128x128 tile, BK=8, 256 threads, 8x8 microtile.
// =====================================================================
__global__ void __launch_bounds__(256) wgemm_kernel(
    const float* __restrict__ W,     // [M][K] row-major
    const float* __restrict__ bias,  // [M]
    const float* __restrict__ X,     // [batch][K][NPIX]
    const float* __restrict__ sc,    // [batch][K] or null (fused GN scale)
    const float* __restrict__ tb,    // [batch][K] or null (fused GN shift)
    const float* __restrict__ res,   // [batch][M][NPIX] or null
    float* __restrict__ C,           // [batch][M][NPIX]
    int Kdim)
{
    __shared__ float As[8][128];
    __shared__ float Bs[8][128];

    const int bz = blockIdx.z;
    const float* Xb = X + (size_t)bz * Kdim * NPIX;
    float*       Cb = C;  // offset below
    const float* scb = sc ? sc + bz * Kdim : nullptr;
    const float* tbb = tb ? tb + bz * Kdim : nullptr;

    const int o0 = blockIdx.y * 128;
    const int n0 = blockIdx.x * 128;
    const int tid = threadIdx.x;

    const int a_row = tid >> 1;          // 0..127
    const int a_col = (tid & 1) * 4;     // 0 or 4
    const int b_row = tid >> 5;          // 0..7
    const int b_col = (tid & 31) * 4;    // 0..124
    const int ty = tid >> 4, tx = tid & 15;

    float acc[8][8] = {};

    for (int k0 = 0; k0 < Kdim; k0 += 8) {
        float4 av = *(const float4*)&W[(size_t)(o0 + a_row) * Kdim + k0 + a_col];
        As[a_col + 0][a_row] = av.x;
        As[a_col + 1][a_row] = av.y;
        As[a_col + 2][a_row] = av.z;
        As[a_col + 3][a_row] = av.w;
        float4 bv = *(const float4*)&Xb[(size_t)(k0 + b_row) * NPIX + n0 + b_col];
        if (scb) {
            const float s = scb[k0 + b_row];
            const float t = tbb[k0 + b_row];
            bv.x = bv.x * s + t; bv.y = bv.y * s + t;
            bv.z = bv.z * s + t; bv.w = bv.w * s + t;
        }
        *(float4*)&Bs[b_row][b_col] = bv;
        __syncthreads();

        #pragma unroll
        for (int kk = 0; kk < 8; kk++) {
            float a[8], bb[8];
            #pragma unroll
            for (int i = 0; i < 8; i++) a[i]  = As[kk][ty * 8 + i];
            #pragma unroll
            for (int j = 0; j < 8; j++) bb[j] = Bs[kk][tx * 8 + j];
            #pragma unroll
            for (int i = 0; i < 8; i++)
                #pragma unroll
                for (int j = 0; j < 8; j++)
                    acc[i][j] += a[i] * bb[j];
        }
        __syncthreads();
    }

    const int Mstride = gridDim.y * 128;
    Cb = C + (size_t)bz * Mstride * NPIX;
    const float* Rb = res ? res + (size_t)bz * Mstride * NPIX : nullptr;

    #pragma unroll
    for (int i = 0; i < 8; i++) {
        const int o = o0 + ty * 8 + i;
        const float bvs = bias[o];
        #pragma unroll
        for (int j = 0; j < 8; j++) {
            const int n = n0 + tx * 8 + j;
            float v = acc[i][j] + bvs;
            if (Rb) v += Rb[(size_t)o * NPIX + n];
            Cb[(size_t)o * NPIX + n] = v;
        }
    }
}

// =====================================================================
// 3) QK^T chunk: S[bhl][n][m] = scale * sum_d q[d][n]*k[d][m]
// =====================================================================
__global__ void __launch_bounds__(256) qk_kernel(int bh0)
{
    __shared__ float Qs[8][128];
    __shared__ float Ks[8][128];

    const int bhl = blockIdx.z;          // local chunk index
    const int bh = bh0 + bhl;
    const int b = bh >> 3, h = bh & 7;
    const float* q = g_qkv + ((size_t)b * 3 * CH + h * HD) * NPIX;
    const float* k = g_qkv + ((size_t)b * 3 * CH + CH + h * HD) * NPIX;
    float* Sb = g_S + (size_t)bhl * NPIX * NPIX;

    const int n0 = blockIdx.y * 128;
    const int m0 = blockIdx.x * 128;
    const int tid = threadIdx.x;
    const int l_row = tid >> 5, l_col = (tid & 31) * 4;
    const int ty = tid >> 4, tx = tid & 15;

    float acc[8][8] = {};

    for (int d0 = 0; d0 < HD; d0 += 8) {
        *(float4*)&Qs[l_row][l_col] =
            *(const float4*)&q[(size_t)(d0 + l_row) * NPIX + n0 + l_col];
        *(float4*)&Ks[l_row][l_col] =
            *(const float4*)&k[(size_t)(d0 + l_row) * NPIX + m0 + l_col];
        __syncthreads();

        #pragma unroll
        for (int kk = 0; kk < 8; kk++) {
            float a[8], bb[8];
            #pragma unroll
            for (int i = 0; i < 8; i++) a[i]  = Qs[kk][ty * 8 + i];
            #pragma unroll
            for (int j = 0; j < 8; j++) bb[j] = Ks[kk][tx * 8 + j];
            #pragma unroll
            for (int i = 0; i < 8; i++)
                #pragma unroll
                for (int j = 0; j < 8; j++)
                    acc[i][j] += a[i] * bb[j];
        }
        __syncthreads();
    }

    const float scale = 0.125f;   // hd^-0.5 = 1/8
    #pragma unroll
    for (int i = 0; i < 8; i++)
        #pragma unroll
        for (int j = 0; j < 8; j++)
            Sb[(size_t)(n0 + ty * 8 + i) * NPIX + m0 + tx * 8 + j] = acc[i][j] * scale;
}

// =====================================================================
// 4) Row softmax over m (length 1024). grid(1024, CHB), 128 threads.
// =====================================================================
__global__ void __launch_bounds__(128) softmax_kernel()
{
    float* r = g_S + ((size_t)blockIdx.y * NPIX + blockIdx.x) * NPIX;
    const int t = threadIdx.x;
    __shared__ float red[128];

    float v[8];
    float m = -1e30f;
    #pragma unroll
    for (int i = 0; i < 8; i++) {
        v[i] = r[t + i * 128];
        m = fmaxf(m, v[i]);
    }
    red[t] = m; __syncthreads();
    for (int st = 64; st > 0; st >>= 1) {
        if (t < st) red[t] = fmaxf(red[t], red[t + st]);
        __syncthreads();
    }
    m = red[0];
    __syncthreads();

    float s = 0.f;
    #pragma unroll
    for (int i = 0; i < 8; i++) {
        v[i] = __expf(v[i] - m);
        s += v[i];
    }
    red[t] = s; __syncthreads();
    for (int st = 64; st > 0; st >>= 1) {
        if (t < st) red[t] += red[t + st];
        __syncthreads();
    }
    const float inv = 1.f / red[0];
    #pragma unroll
    for (int i = 0; i < 8; i++) r[t + i * 128] = v[i] * inv;
}

// =====================================================================
// 5) AV chunk: ao[bh][d][n] = sum_m P[n][m] * v[d][m]
//    Tile 64(d) x 128(n), BK=16 over m, 256 threads, 4x8 microtile.
//    n-mapping stride-16 for conflict-free Ps reads.
// =====================================================================
__global__ void __launch_bounds__(256) av_kernel(int bh0)
{
    __shared__ float Vs[16][64];    // Vs[k][d]
    __shared__ float Ps[16][128];   // Ps[k][n]

    const int bhl = blockIdx.y;
    const int bh = bh0 + bhl;
    const int b = bh >> 3, h = bh & 7;
    const float* V  = g_qkv + ((size_t)b * 3 * CH + 2 * CH + h * HD) * NPIX;
    const float* Sb = g_S + (size_t)bhl * NPIX * NPIX;
    float* ao = g_ao + ((size_t)b * CH + h * HD) * NPIX;

    const int n0 = blockIdx.x * 128;
    const int tid = threadIdx.x;
    const int trow = tid >> 4;          // 0..15 -> d rows * 4
    const int tcol = tid & 15;          // n cols, stride-16
    const int vr = tid >> 2;            // 0..63
    const int vk = (tid & 3) * 4;       // 0..12

    float acc[4][8] = {};

    for (int m0 = 0; m0 < NPIX; m0 += 16) {
        float4 vv = *(const float4*)&V[(size_t)vr * NPIX + m0 + vk];
        Vs[vk + 0][vr] = vv.x;
        Vs[vk + 1][vr] = vv.y;
        Vs[vk + 2][vr] = vv.z;
        Vs[vk + 3][vr] = vv.w;
        #pragma unroll
        for (int l = 0; l < 2; l++) {
            int idx = tid * 2 + l;      // 0..511
            int pr  = idx >> 2;         // n row 0..127
            int pk  = (idx & 3) * 4;
            float4 pv = *(const float4*)&Sb[(size_t)(n0 + pr) * NPIX + m0 + pk];
            Ps[pk + 0][pr] = pv.x;
            Ps[pk + 1][pr] = pv.y;
            Ps[pk + 2][pr] = pv.z;
            Ps[pk + 3][pr] = pv.w;
        }
        __syncthreads();

        #pragma unroll
        for (int kk = 0; kk < 16; kk++) {
            float a[4], bb[8];
            #pragma unroll
            for (int i = 0; i < 4; i++) a[i]  = Vs[kk][trow * 4 + i];
            #pragma unroll
            for (int j = 0; j < 8; j++) bb[j] = Ps[kk][tcol + 16 * j];
            #pragma unroll
            for (int i = 0; i < 4; i++)
                #pragma unroll
                for (int j = 0; j < 8; j++)
                    acc[i][j] += a[i] * bb[j];
        }
        __syncthreads();
    }

    #pragma unroll
    for (int i = 0; i < 4; i++)
        #pragma unroll
        for (int j = 0; j < 8; j++)
            ao[(size_t)(trow * 4 + i) * NPIX + n0 + tcol + 16 * j] = acc[i][j];
}

// =====================================================================
// launcher
// =====================================================================
extern "C" void kernel_launch(void* const* d_in, const int* in_sizes, int n_in,
                              void* d_out, int out_size)
{
    const float* x      = (const float*)d_in[0];
    const float* norm_w = (const float*)d_in[1];
    const float* norm_b = (const float*)d_in[2];
    const float* qkv_w  = (const float*)d_in[3];
    const float* qkv_b  = (const float*)d_in[4];
    const float* proj_w = (const float*)d_in[5];
    const float* proj_b = (const float*)d_in[6];
    float* out = (float*)d_out;

    float *qkv_p, *sc_p, *tb_p, *ao_p;
    cudaGetSymbolAddress((void**)&qkv_p, g_qkv);
    cudaGetSymbolAddress((void**)&sc_p,  g_sc);
    cudaGetSymbolAddress((void**)&tb_p,  g_tb);
    cudaGetSymbolAddress((void**)&ao_p,  g_ao);

    // 1) GroupNorm stats -> per-channel affine
    gn_stats_kernel<<<BATCH * GROUPS, 256>>>(x, norm_w, norm_b);

    // 2) QKV projection with fused GN: M=1536, K=512
    {
        dim3 grid(NPIX / 128, (3 * CH) / 128, BATCH);
        wgemm_kernel<<<grid, 256>>>(qkv_w, qkv_b, x, sc_p, tb_p,
                                    nullptr, qkv_p, CH);
    }

    // 3-5) attention in chunks of CHB (b,h) pairs, reusing the S buffer.
    for (int bh0 = 0; bh0 < BATCH * HEADS; bh0 += CHB) {
        {
            dim3 grid(NPIX / 128, NPIX / 128, CHB);
            qk_kernel<<<grid, 256>>>(bh0);
        }
        {
            dim3 grid(NPIX, CHB);
            softmax_kernel<<<grid, 128>>>();
        }
        {
            dim3 grid(NPIX / 128, CHB);
            av_kernel<<<grid, 256>>>(bh0);
        }
    }

    // 6) proj + bias + residual: M=512, K=512
    {
        dim3 grid(NPIX / 128, CH / 128, BATCH);
        wgemm_kernel<<<grid, 256>>>(proj_w, proj_b, ao_p, nullptr, nullptr,
                                    x, out, CH);
    }
}

// round 4
// speedup vs baseline: 1.6881x; 1.6881x over previous
#include <cuda_runtime.h>

// Problem constants
#define BATCH   8
#define CH      512
#define HEADS   8
#define HD      64
#define GROUPS  32
#define CPG     16
#define NPIX    1024
#define EPS_GN  1e-6f
#define CHB     16          // (b,h) pairs per attention chunk
#define BK      16

typedef unsigned long long ull;

// -------- scratch (device globals) : 48+64+16 = 128 MB ----------
__device__ float g_qkv[BATCH * 3 * CH * NPIX];        // 48 MB
__device__ float g_S  [CHB * NPIX * NPIX];            // 64 MB (reused 4x)
__device__ float g_ao [BATCH * CH * NPIX];            // 16 MB
__device__ float g_sc [BATCH * CH];
__device__ float g_tb [BATCH * CH];

// -------- packed f32x2 helpers (FFMA2 — 2x fp32 rate, full precision) ----
__device__ __forceinline__ ull pack2(float lo, float hi) {
    ull r; asm("mov.b64 %0, {%1, %2};" : "=l"(r) : "f"(lo), "f"(hi)); return r;
}
__device__ __forceinline__ void ffma2(ull& d, ull a, ull b) {
    asm("fma.rn.f32x2 %0, %1, %2, %0;" : "+l"(d) : "l"(a), "l"(b));
}
__device__ __forceinline__ float f2lo(ull v) { return __uint_as_float((unsigned)v); }
__device__ __forceinline__ float f2hi(ull v) { return __uint_as_float((unsigned)(v >> 32)); }

// =====================================================================
// 1) GroupNorm stats -> per-(b,c) affine (s,t): xn = x*s + t
// =====================================================================
__global__ void __launch_bounds__(256) gn_stats_kernel(
    const float* __restrict__ x,
    const float* __restrict__ gamma,
    const float* __restrict__ beta)
{
    const int bg = blockIdx.x;
    const int b  = bg / GROUPS;
    const int g  = bg % GROUPS;
    const int elems = CPG * NPIX;
    const float* xp = x + ((size_t)b * CH + g * CPG) * NPIX;

    float s = 0.f, sq = 0.f;
    for (int i = threadIdx.x; i < elems; i += 256) {
        float v = xp[i];
        s += v; sq += v * v;
    }
    #pragma unroll
    for (int o = 16; o > 0; o >>= 1) {
        s  += __shfl_xor_sync(0xffffffffu, s,  o);
        sq += __shfl_xor_sync(0xffffffffu, sq, o);
    }
    __shared__ float rs[8], rq[8];
    if ((threadIdx.x & 31) == 0) { rs[threadIdx.x >> 5] = s; rq[threadIdx.x >> 5] = sq; }
    __syncthreads();
    float S = 0.f, Q = 0.f;
    #pragma unroll
    for (int i = 0; i < 8; i++) { S += rs[i]; Q += rq[i]; }

    const float mean = S * (1.f / elems);
    const float var  = Q * (1.f / elems) - mean * mean;
    const float inv  = rsqrtf(var + EPS_GN);

    if (threadIdx.x < CPG) {
        const int ch = g * CPG + threadIdx.x;
        const float sc = inv * gamma[ch];
        g_sc[b * CH + ch] = sc;
        g_tb[b * CH + ch] = beta[ch] - mean * sc;
    }
}

// =====================================================================
// 2) Weight GEMM (f32x2): C[b][o][n] = sum_c W[o][c]*(X*s+t) + bias (+res)
//    128x128 tile, BK=16, 256 threads, 8x8 microtile, reg prefetch.
// =====================================================================
__global__ void __launch_bounds__(256) wgemm_kernel(
    const float* __restrict__ W,     // [M][K]
    const float* __restrict__ bias,  // [M]
    const float* __restrict__ X,     // [batch][K][NPIX]
    const float* __restrict__ sc,    // [batch][K] or null
    const float* __restrict__ tb,    // [batch][K] or null
    const float* __restrict__ res,   // [batch][M][NPIX] or null
    float* __restrict__ C,           // [batch][M][NPIX]
    int Mdim, int Kdim)
{
    __shared__ float As[BK][128];
    __shared__ float Bs[BK][128];

    const int bz = blockIdx.z;
    const float* Xb = X + (size_t)bz * Kdim * NPIX;
    const float* scb = sc ? sc + bz * Kdim : nullptr;
    const float* tbb = tb ? tb + bz * Kdim : nullptr;

    const int o0 = blockIdx.y * 128;
    const int n0 = blockIdx.x * 128;
    const int tid = threadIdx.x;

    const int a_row = tid >> 1;          // 0..127
    const int a_k   = (tid & 1) * 8;     // 0 or 8
    const int b_k   = tid >> 4;          // 0..15
    const int b_col = (tid & 15) * 8;
    const int ty = tid >> 4, tx = tid & 15;

    const float* wp = &W[(size_t)(o0 + a_row) * Kdim + a_k];
    const float* xp = &Xb[(size_t)b_k * NPIX + n0 + b_col];

    float4 pa0 = *(const float4*)(wp);
    float4 pa1 = *(const float4*)(wp + 4);
    float4 pb0 = *(const float4*)(xp);
    float4 pb1 = *(const float4*)(xp + 4);
    float s_ = 1.f, t_ = 0.f;
    if (scb) { s_ = scb[b_k]; t_ = tbb[b_k]; }

    ull acc[4][8];
    #pragma unroll
    for (int p = 0; p < 4; p++)
        #pragma unroll
        for (int j = 0; j < 8; j++) acc[p][j] = 0ull;

    for (int k0 = 0; k0 < Kdim; k0 += BK) {
        As[a_k + 0][a_row] = pa0.x; As[a_k + 1][a_row] = pa0.y;
        As[a_k + 2][a_row] = pa0.z; As[a_k + 3][a_row] = pa0.w;
        As[a_k + 4][a_row] = pa1.x; As[a_k + 5][a_row] = pa1.y;
        As[a_k + 6][a_row] = pa1.z; As[a_k + 7][a_row] = pa1.w;
        float4 vb0 = pb0, vb1 = pb1;
        if (scb) {
            vb0.x = vb0.x * s_ + t_; vb0.y = vb0.y * s_ + t_;
            vb0.z = vb0.z * s_ + t_; vb0.w = vb0.w * s_ + t_;
            vb1.x = vb1.x * s_ + t_; vb1.y = vb1.y * s_ + t_;
            vb1.z = vb1.z * s_ + t_; vb1.w = vb1.w * s_ + t_;
        }
        *(float4*)&Bs[b_k][b_col]     = vb0;
        *(float4*)&Bs[b_k][b_col + 4] = vb1;
        __syncthreads();

        if (k0 + BK < Kdim) {                    // prefetch next tile
            pa0 = *(const float4*)(wp + k0 + BK);
            pa1 = *(const float4*)(wp + k0 + BK + 4);
            pb0 = *(const float4*)(xp + (size_t)(k0 + BK) * NPIX);
            pb1 = *(const float4*)(xp + (size_t)(k0 + BK) * NPIX + 4);
            if (scb) { s_ = scb[k0 + BK + b_k]; t_ = tbb[k0 + BK + b_k]; }
        }

        #pragma unroll
        for (int kk = 0; kk < BK; kk++) {
            float4 af0 = *(const float4*)&As[kk][ty * 8];
            float4 af1 = *(const float4*)&As[kk][ty * 8 + 4];
            float4 bf0 = *(const float4*)&Bs[kk][tx * 8];
            float4 bf1 = *(const float4*)&Bs[kk][tx * 8 + 4];
            ull ap[4] = { pack2(af0.x, af0.y), pack2(af0.z, af0.w),
                          pack2(af1.x, af1.y), pack2(af1.z, af1.w) };
            ull bp[8] = { pack2(bf0.x, bf0.x), pack2(bf0.y, bf0.y),
                          pack2(bf0.z, bf0.z), pack2(bf0.w, bf0.w),
                          pack2(bf1.x, bf1.x), pack2(bf1.y, bf1.y),
                          pack2(bf1.z, bf1.z), pack2(bf1.w, bf1.w) };
            #pragma unroll
            for (int p = 0; p < 4; p++)
                #pragma unroll
                for (int j = 0; j < 8; j++)
                    ffma2(acc[p][j], ap[p], bp[j]);
        }
        __syncthreads();
    }

    float* Cb = C + (size_t)bz * Mdim * NPIX;
    const float* Rb = res ? res + (size_t)bz * Mdim * NPIX : nullptr;

    #pragma unroll
    for (int p = 0; p < 4; p++) {
        #pragma unroll
        for (int half = 0; half < 2; half++) {
            const int o = o0 + ty * 8 + 2 * p + half;
            const float bvs = bias[o];
            float4 r0, r1;
            if (half == 0) {
                r0 = make_float4(f2lo(acc[p][0]), f2lo(acc[p][1]), f2lo(acc[p][2]), f2lo(acc[p][3]));
                r1 = make_float4(f2lo(acc[p][4]), f2lo(acc[p][5]), f2lo(acc[p][6]), f2lo(acc[p][7]));
            } else {
                r0 = make_float4(f2hi(acc[p][0]), f2hi(acc[p][1]), f2hi(acc[p][2]), f2hi(acc[p][3]));
                r1 = make_float4(f2hi(acc[p][4]), f2hi(acc[p][5]), f2hi(acc[p][6]), f2hi(acc[p][7]));
            }
            r0.x += bvs; r0.y += bvs; r0.z += bvs; r0.w += bvs;
            r1.x += bvs; r1.y += bvs; r1.z += bvs; r1.w += bvs;
            float* cp = &Cb[(size_t)o * NPIX + n0 + tx * 8];
            if (Rb) {
                const float* rp = &Rb[(size_t)o * NPIX + n0 + tx * 8];
                float4 q0 = *(const float4*)(rp);
                float4 q1 = *(const float4*)(rp + 4);
                r0.x += q0.x; r0.y += q0.y; r0.z += q0.z; r0.w += q0.w;
                r1.x += q1.x; r1.y += q1.y; r1.z += q1.z; r1.w += q1.w;
            }
            *(float4*)(cp)     = r0;
            *(float4*)(cp + 4) = r1;
        }
    }
}

// =====================================================================
// 3) QK^T chunk (f32x2): S[bhl][n][m] = 0.125 * sum_d q[d][n]*k[d][m]
// =====================================================================
__global__ void __launch_bounds__(256) qk_kernel(int bh0)
{
    __shared__ float Qs[BK][128];
    __shared__ float Ks[BK][128];

    const int bhl = blockIdx.z;
    const int bh = bh0 + bhl;
    const int b = bh >> 3, h = bh & 7;
    const float* q = g_qkv + ((size_t)b * 3 * CH + h * HD) * NPIX;
    const float* k = g_qkv + ((size_t)b * 3 * CH + CH + h * HD) * NPIX;
    float* Sb = g_S + (size_t)bhl * NPIX * NPIX;

    const int n0 = blockIdx.y * 128;
    const int m0 = blockIdx.x * 128;
    const int tid = threadIdx.x;
    const int l_k   = tid >> 4;           // 0..15
    const int l_col = (tid & 15) * 8;
    const int ty = tid >> 4, tx = tid & 15;

    const float* qp = &q[(size_t)l_k * NPIX + n0 + l_col];
    const float* kp = &k[(size_t)l_k * NPIX + m0 + l_col];

    float4 pq0 = *(const float4*)(qp);
    float4 pq1 = *(const float4*)(qp + 4);
    float4 pk0 = *(const float4*)(kp);
    float4 pk1 = *(const float4*)(kp + 4);

    ull acc[4][8];
    #pragma unroll
    for (int p = 0; p < 4; p++)
        #pragma unroll
        for (int j = 0; j < 8; j++) acc[p][j] = 0ull;

    for (int d0 = 0; d0 < HD; d0 += BK) {
        *(float4*)&Qs[l_k][l_col]     = pq0;
        *(float4*)&Qs[l_k][l_col + 4] = pq1;
        *(float4*)&Ks[l_k][l_col]     = pk0;
        *(float4*)&Ks[l_k][l_col + 4] = pk1;
        __syncthreads();

        if (d0 + BK < HD) {
            pq0 = *(const float4*)(qp + (size_t)(d0 + BK) * NPIX);
            pq1 = *(const float4*)(qp + (size_t)(d0 + BK) * NPIX + 4);
            pk0 = *(const float4*)(kp + (size_t)(d0 + BK) * NPIX);
            pk1 = *(const float4*)(kp + (size_t)(d0 + BK) * NPIX + 4);
        }

        #pragma unroll
        for (int kk = 0; kk < BK; kk++) {
            float4 af0 = *(const float4*)&Qs[kk][ty * 8];
            float4 af1 = *(const float4*)&Qs[kk][ty * 8 + 4];
            float4 bf0 = *(const float4*)&Ks[kk][tx * 8];
            float4 bf1 = *(const float4*)&Ks[kk][tx * 8 + 4];
            ull ap[4] = { pack2(af0.x, af0.y), pack2(af0.z, af0.w),
                          pack2(af1.x, af1.y), pack2(af1.z, af1.w) };
            ull bp[8] = { pack2(bf0.x, bf0.x), pack2(bf0.y, bf0.y),
                          pack2(bf0.z, bf0.z), pack2(bf0.w, bf0.w),
                          pack2(bf1.x, bf1.x), pack2(bf1.y, bf1.y),
                          pack2(bf1.z, bf1.z), pack2(bf1.w, bf1.w) };
            #pragma unroll
            for (int p = 0; p < 4; p++)
                #pragma unroll
                for (int j = 0; j < 8; j++)
                    ffma2(acc[p][j], ap[p], bp[j]);
        }
        __syncthreads();
    }

    const float scale = 0.125f;
    #pragma unroll
    for (int p = 0; p < 4; p++) {
        #pragma unroll
        for (int half = 0; half < 2; half++) {
            const int n = n0 + ty * 8 + 2 * p + half;
            float4 r0, r1;
            if (half == 0) {
                r0 = make_float4(f2lo(acc[p][0]), f2lo(acc[p][1]), f2lo(acc[p][2]), f2lo(acc[p][3]));
                r1 = make_float4(f2lo(acc[p][4]), f2lo(acc[p][5]), f2lo(acc[p][6]), f2lo(acc[p][7]));
            } else {
                r0 = make_float4(f2hi(acc[p][0]), f2hi(acc[p][1]), f2hi(acc[p][2]), f2hi(acc[p][3]));
                r1 = make_float4(f2hi(acc[p][4]), f2hi(acc[p][5]), f2hi(acc[p][6]), f2hi(acc[p][7]));
            }
            r0.x *= scale; r0.y *= scale; r0.z *= scale; r0.w *= scale;
            r1.x *= scale; r1.y *= scale; r1.z *= scale; r1.w *= scale;
            float* sp = &Sb[(size_t)n * NPIX + m0 + tx * 8];
            *(float4*)(sp)     = r0;
            *(float4*)(sp + 4) = r1;
        }
    }
}

// =====================================================================
// 4) Row softmax over m=1024. grid(1024, CHB), 256 threads, float4.
// =====================================================================
__global__ void __launch_bounds__(256) softmax_kernel()
{
    float* r = g_S + ((size_t)blockIdx.y * NPIX + blockIdx.x) * NPIX;
    const int t = threadIdx.x;
    __shared__ float red_m[8], red_s[8];

    float4 v = *(float4*)&r[t * 4];
    float m = fmaxf(fmaxf(v.x, v.y), fmaxf(v.z, v.w));
    #pragma unroll
    for (int o = 16; o > 0; o >>= 1)
        m = fmaxf(m, __shfl_xor_sync(0xffffffffu, m, o));
    if ((t & 31) == 0) red_m[t >> 5] = m;
    __syncthreads();
    m = red_m[0];
    #pragma unroll
    for (int i = 1; i < 8; i++) m = fmaxf(m, red_m[i]);

    v.x = __expf(v.x - m); v.y = __expf(v.y - m);
    v.z = __expf(v.z - m); v.w = __expf(v.w - m);
    float s = v.x + v.y + v.z + v.w;
    #pragma unroll
    for (int o = 16; o > 0; o >>= 1)
        s += __shfl_xor_sync(0xffffffffu, s, o);
    if ((t & 31) == 0) red_s[t >> 5] = s;
    __syncthreads();
    s = 0.f;
    #pragma unroll
    for (int i = 0; i < 8; i++) s += red_s[i];

    const float inv = 1.f / s;
    v.x *= inv; v.y *= inv; v.z *= inv; v.w *= inv;
    *(float4*)&r[t * 4] = v;
}

// =====================================================================
// 5) AV chunk (f32x2): ao[bh][d][n] = sum_m P[n][m] * v[d][m]
//    Tile 64(d) x 128(n), BK=16 over m, 128 threads, 8x8 microtile.
// =====================================================================
__global__ void __launch_bounds__(128) av_kernel(int bh0)
{
    __shared__ float Vs[BK][64];     // Vs[k][d]
    __shared__ float Ps[BK][128];    // Ps[k][n]

    const int bhl = blockIdx.y;
    const int bh = bh0 + bhl;
    const int b = bh >> 3, h = bh & 7;
    const float* V  = g_qkv + ((size_t)b * 3 * CH + 2 * CH + h * HD) * NPIX;
    const float* Sb = g_S + (size_t)bhl * NPIX * NPIX;
    float* ao = g_ao + ((size_t)b * CH + h * HD) * NPIX;

    const int n0 = blockIdx.x * 128;
    const int tid = threadIdx.x;
    const int ty = tid >> 4, tx = tid & 15;     // microtile: d rows ty*8.., n cols tx*8..
    const int v_row = tid >> 1;                 // 0..63
    const int v_k   = (tid & 1) * 8;            // 0 or 8
    const int p_row = tid;                      // 0..127 (n index)

    const float* vp = &V[(size_t)v_row * NPIX + v_k];
    const float* sp = &Sb[(size_t)(n0 + p_row) * NPIX];

    // prefetch first tile
    float4 pv0 = *(const float4*)(vp);
    float4 pv1 = *(const float4*)(vp + 4);
    float4 ps0 = *(const float4*)(sp);
    float4 ps1 = *(const float4*)(sp + 4);
    float4 ps2 = *(const float4*)(sp + 8);
    float4 ps3 = *(const float4*)(sp + 12);

    ull acc[4][8];
    #pragma unroll
    for (int p = 0; p < 4; p++)
        #pragma unroll
        for (int j = 0; j < 8; j++) acc[p][j] = 0ull;

    for (int m0 = 0; m0 < NPIX; m0 += BK) {
        Vs[v_k + 0][v_row] = pv0.x; Vs[v_k + 1][v_row] = pv0.y;
        Vs[v_k + 2][v_row] = pv0.z; Vs[v_k + 3][v_row] = pv0.w;
        Vs[v_k + 4][v_row] = pv1.x; Vs[v_k + 5][v_row] = pv1.y;
        Vs[v_k + 6][v_row] = pv1.z; Vs[v_k + 7][v_row] = pv1.w;
        Ps[ 0][p_row] = ps0.x; Ps[ 1][p_row] = ps0.y;
        Ps[ 2][p_row] = ps0.z; Ps[ 3][p_row] = ps0.w;
        Ps[ 4][p_row] = ps1.x; Ps[ 5][p_row] = ps1.y;
        Ps[ 6][p_row] = ps1.z; Ps[ 7][p_row] = ps1.w;
        Ps[ 8][p_row] = ps2.x; Ps[ 9][p_row] = ps2.y;
        Ps[10][p_row] = ps2.z; Ps[11][p_row] = ps2.w;
        Ps[12][p_row] = ps3.x; Ps[13][p_row] = ps3.y;
        Ps[14][p_row] = ps3.z; Ps[15][p_row] = ps3.w;
        __syncthreads();

        if (m0 + BK < NPIX) {
            pv0 = *(const float4*)(vp + m0 + BK);
            pv1 = *(const float4*)(vp + m0 + BK + 4);
            ps0 = *(const float4*)(sp + m0 + BK);
            ps1 = *(const float4*)(sp + m0 + BK + 4);
            ps2 = *(const float4*)(sp + m0 + BK + 8);
            ps3 = *(const float4*)(sp + m0 + BK + 12);
        }

        #pragma unroll
        for (int kk = 0; kk < BK; kk++) {
            float4 af0 = *(const float4*)&Vs[kk][ty * 8];
            float4 af1 = *(const float4*)&Vs[kk][ty * 8 + 4];
            float4 bf0 = *(const float4*)&Ps[kk][tx * 8];
            float4 bf1 = *(const float4*)&Ps[kk][tx * 8 + 4];
            ull ap[4] = { pack2(af0.x, af0.y), pack2(af0.z, af0.w),
                          pack2(af1.x, af1.y), pack2(af1.z, af1.w) };
            ull bp[8] = { pack2(bf0.x, bf0.x), pack2(bf0.y, bf0.y),
                          pack2(bf0.z, bf0.z), pack2(bf0.w, bf0.w),
                          pack2(bf1.x, bf1.x), pack2(bf1.y, bf1.y),
                          pack2(bf1.z, bf1.z), pack2(bf1.w, bf1.w) };
            #pragma unroll
            for (int p = 0; p < 4; p++)
                #pragma unroll
                for (int j = 0; j < 8; j++)
                    ffma2(acc[p][j], ap[p], bp[j]);
        }
        __syncthreads();
    }

    #pragma unroll
    for (int p = 0; p < 4; p++) {
        #pragma unroll
        for (int half = 0; half < 2; half++) {
            const int d = ty * 8 + 2 * p + half;
            float4 r0, r1;
            if (half == 0) {
                r0 = make_float4(f2lo(acc[p][0]), f2lo(acc[p][1]), f2lo(acc[p][2]), f2lo(acc[p][3]));
                r1 = make_float4(f2lo(acc[p][4]), f2lo(acc[p][5]), f2lo(acc[p][6]), f2lo(acc[p][7]));
            } else {
                r0 = make_float4(f2hi(acc[p][0]), f2hi(acc[p][1]), f2hi(acc[p][2]), f2hi(acc[p][3]));
                r1 = make_float4(f2hi(acc[p][4]), f2hi(acc[p][5]), f2hi(acc[p][6]), f2hi(acc[p][7]));
            }
            float* op = &ao[(size_t)d * NPIX + n0 + tx * 8];
            *(float4*)(op)     = r0;
            *(float4*)(op + 4) = r1;
        }
    }
}

// =====================================================================
// launcher
// =====================================================================
extern "C" void kernel_launch(void* const* d_in, const int* in_sizes, int n_in,
                              void* d_out, int out_size)
{
    const float* x      = (const float*)d_in[0];
    const float* norm_w = (const float*)d_in[1];
    const float* norm_b = (const float*)d_in[2];
    const float* qkv_w  = (const float*)d_in[3];
    const float* qkv_b  = (const float*)d_in[4];
    const float* proj_w = (const float*)d_in[5];
    const float* proj_b = (const float*)d_in[6];
    float* out = (float*)d_out;

    float *qkv_p, *sc_p, *tb_p, *ao_p;
    cudaGetSymbolAddress((void**)&qkv_p, g_qkv);
    cudaGetSymbolAddress((void**)&sc_p,  g_sc);
    cudaGetSymbolAddress((void**)&tb_p,  g_tb);
    cudaGetSymbolAddress((void**)&ao_p,  g_ao);

    // 1) GroupNorm stats
    gn_stats_kernel<<<BATCH * GROUPS, 256>>>(x, norm_w, norm_b);

    // 2) QKV projection (GN fused): M=1536, K=512
    {
        dim3 grid(NPIX / 128, (3 * CH) / 128, BATCH);
        wgemm_kernel<<<grid, 256>>>(qkv_w, qkv_b, x, sc_p, tb_p,
                                    nullptr, qkv_p, 3 * CH, CH);
    }

    // 3-5) attention in chunks of CHB (b,h) pairs
    for (int bh0 = 0; bh0 < BATCH * HEADS; bh0 += CHB) {
        {
            dim3 grid(NPIX / 128, NPIX / 128, CHB);
            qk_kernel<<<grid, 256>>>(bh0);
        }
        {
            dim3 grid(NPIX, CHB);
            softmax_kernel<<<grid, 256>>>();
        }
        {
            dim3 grid(NPIX / 128, CHB);
            av_kernel<<<grid, 128>>>(bh0);
        }
    }

    // 6) proj + bias + residual: M=512, K=512
    {
        dim3 grid(NPIX / 128, CH / 128, BATCH);
        wgemm_kernel<<<grid, 256>>>(proj_w, proj_b, ao_p, nullptr, nullptr,
                                    x, out, CH, CH);
    }
}